// round 3
// baseline (speedup 1.0000x reference)
// RBF kernel regression: out[B,F] = exp(-||z-x||^2/2) @ alpha
// B=2048, N=100000, D=64, F=16, fp32.
// Strategy: -sqdist/2 = z.x - 0.5||z||^2 - 0.5||x||^2.
//   prep kernel: half squared norms of all rows.
//   main kernel: fused tiled GEMM (128b x 64n tiles, k=64) using packed
//     fma.rn.f32x2 (sm_103a FFMA2, 2x fp32 rate), epilogue exp, then an
//     in-block second GEMM K_tile @ alpha_tile through shared staging,
//     accumulators held in registers across n-tiles. Deterministic partial
//     buffer + reduce (no float atomics).
#include <cuda_runtime.h>

#define DD 64
#define FF 16
#define BT 128
#define NT 64
#define BP 132   // zs row pad (floats)
#define NP 66    // xs row pad
#define EP 68    // es row pad
#define NBX 64   // number of n-chunk blocks
#define MAXB 2048
#define MAXN 100224

__device__ float g_xsq[MAXN];
__device__ float g_zsq[MAXB];
__device__ float g_part[(size_t)NBX * MAXB * FF];

struct __align__(16) SmemT {
    float zs[DD][BP];    // z tile, k-major
    float xs[DD][NP];    // x tile, k-major
    float es[BT][EP];    // exp(K) staging tile
    float as[NT][FF];    // alpha tile
    float zsq[BT];
    float xsq[NT];
};

static __device__ __forceinline__ float2 ffma2(float2 a, float2 b, float2 c) {
    unsigned long long ra = *reinterpret_cast<unsigned long long*>(&a);
    unsigned long long rb = *reinterpret_cast<unsigned long long*>(&b);
    unsigned long long rc = *reinterpret_cast<unsigned long long*>(&c);
    unsigned long long rd;
    asm("fma.rn.f32x2 %0, %1, %2, %3;" : "=l"(rd) : "l"(ra), "l"(rb), "l"(rc));
    return *reinterpret_cast<float2*>(&rd);
}

__global__ void prep_norms(const float* __restrict__ z,
                           const float* __restrict__ x, int B, int N) {
    int i = blockIdx.x * blockDim.x + threadIdx.x;
    if (i < N) {
        const float4* p = reinterpret_cast<const float4*>(x + (size_t)i * DD);
        float s = 0.f;
#pragma unroll
        for (int q = 0; q < DD / 4; q++) {
            float4 v = p[q];
            s += v.x * v.x + v.y * v.y + v.z * v.z + v.w * v.w;
        }
        g_xsq[i] = 0.5f * s;
    } else if (i < N + B) {
        int b = i - N;
        const float4* p = reinterpret_cast<const float4*>(z + (size_t)b * DD);
        float s = 0.f;
#pragma unroll
        for (int q = 0; q < DD / 4; q++) {
            float4 v = p[q];
            s += v.x * v.x + v.y * v.y + v.z * v.z + v.w * v.w;
        }
        g_zsq[b] = 0.5f * s;
    }
}

__global__ __launch_bounds__(256, 2) void rbf_main(
    const float* __restrict__ z, const float* __restrict__ x,
    const float* __restrict__ alpha, int B, int N, int ntiles, int chunk) {
    extern __shared__ SmemT smem[];
    SmemT* s = smem;
    const int t = threadIdx.x;
    const int tx = t & 15;   // n direction (phase A)
    const int ty = t >> 4;   // b direction (phase A)
    const int b_base = blockIdx.y * BT;
    const int tile0 = blockIdx.x * chunk;
    const int tile1 = min(tile0 + chunk, ntiles);

    // ---- load z tile once: transpose [b][k] -> zs[k][b] ----
#pragma unroll
    for (int r = 0; r < 8; r++) {
        int idx = t + r * 256;          // 0..2047
        int row = idx >> 4, q = idx & 15;
        float4 v = *reinterpret_cast<const float4*>(
            &z[(size_t)(b_base + row) * DD + q * 4]);
        s->zs[q * 4 + 0][row] = v.x;
        s->zs[q * 4 + 1][row] = v.y;
        s->zs[q * 4 + 2][row] = v.z;
        s->zs[q * 4 + 3][row] = v.w;
    }
    if (t < BT) s->zsq[t] = g_zsq[b_base + t];

    // phase-B thread mapping: fixed (b, f-half) across all tiles
    const int bb = t >> 1;
    const int fh = (t & 1) * 8;
    float2 oacc[4];
    oacc[0] = make_float2(0.f, 0.f); oacc[1] = make_float2(0.f, 0.f);
    oacc[2] = make_float2(0.f, 0.f); oacc[3] = make_float2(0.f, 0.f);

    for (int tile = tile0; tile < tile1; ++tile) {
        const int n_base = tile * NT;
        __syncthreads();   // previous phase B done with xs/es/as
        // ---- load x tile (transpose), xsq, alpha tile ----
#pragma unroll
        for (int r = 0; r < 4; r++) {
            int idx = t + r * 256;      // 0..1023
            int nl = idx >> 4, q = idx & 15;
            int ng = n_base + nl;
            float4 v = make_float4(0.f, 0.f, 0.f, 0.f);
            if (ng < N)
                v = *reinterpret_cast<const float4*>(&x[(size_t)ng * DD + q * 4]);
            s->xs[q * 4 + 0][nl] = v.x;
            s->xs[q * 4 + 1][nl] = v.y;
            s->xs[q * 4 + 2][nl] = v.z;
            s->xs[q * 4 + 3][nl] = v.w;
        }
        if (t < NT) {
            int ng = n_base + t;
            s->xsq[t] = (ng < N) ? g_xsq[ng] : 3.0e37f;  // sentinel -> exp = 0
        }
        {
            int nl = t >> 2, c = (t & 3) * 4;
            int ng = n_base + nl;
            float4 v = make_float4(0.f, 0.f, 0.f, 0.f);
            if (ng < N)
                v = *reinterpret_cast<const float4*>(&alpha[(size_t)ng * FF + c]);
            *reinterpret_cast<float4*>(&s->as[nl][c]) = v;
        }
        __syncthreads();

        // ---- phase A: cross = z.x  (8b x 4n per thread, f32x2 paired on n) ----
        float2 acc[8][2];
#pragma unroll
        for (int i = 0; i < 8; i++) {
            acc[i][0] = make_float2(0.f, 0.f);
            acc[i][1] = make_float2(0.f, 0.f);
        }
#pragma unroll 16
        for (int k = 0; k < DD; k++) {
            float4 a0 = *reinterpret_cast<float4*>(&s->zs[k][ty * 8]);
            float4 a1 = *reinterpret_cast<float4*>(&s->zs[k][ty * 8 + 4]);
            float2 b0 = *reinterpret_cast<float2*>(&s->xs[k][tx * 4]);
            float2 b1 = *reinterpret_cast<float2*>(&s->xs[k][tx * 4 + 2]);
            float av[8] = {a0.x, a0.y, a0.z, a0.w, a1.x, a1.y, a1.z, a1.w};
#pragma unroll
            for (int i = 0; i < 8; i++) {
                float2 ad = make_float2(av[i], av[i]);
                acc[i][0] = ffma2(ad, b0, acc[i][0]);
                acc[i][1] = ffma2(ad, b1, acc[i][1]);
            }
        }
        // epilogue: e = exp(cross - hz - hx), stage to es
        float hx0 = s->xsq[tx * 4 + 0];
        float hx1 = s->xsq[tx * 4 + 1];
        float hx2 = s->xsq[tx * 4 + 2];
        float hx3 = s->xsq[tx * 4 + 3];
#pragma unroll
        for (int i = 0; i < 8; i++) {
            float hz = s->zsq[ty * 8 + i];
            float4 ev;
            ev.x = __expf(acc[i][0].x - hz - hx0);
            ev.y = __expf(acc[i][0].y - hz - hx1);
            ev.z = __expf(acc[i][1].x - hz - hx2);
            ev.w = __expf(acc[i][1].y - hz - hx3);
            *reinterpret_cast<float4*>(&s->es[ty * 8 + i][tx * 4]) = ev;
        }
        __syncthreads();

        // ---- phase B: out[b, f] += sum_n es[b][n] * alpha[n][f] ----
#pragma unroll 8
        for (int n = 0; n < NT; n++) {
            float ev = s->es[bb][n];
            float4 a0 = *reinterpret_cast<float4*>(&s->as[n][fh]);
            float4 a1 = *reinterpret_cast<float4*>(&s->as[n][fh + 4]);
            float2 e2 = make_float2(ev, ev);
            oacc[0] = ffma2(e2, make_float2(a0.x, a0.y), oacc[0]);
            oacc[1] = ffma2(e2, make_float2(a0.z, a0.w), oacc[1]);
            oacc[2] = ffma2(e2, make_float2(a1.x, a1.y), oacc[2]);
            oacc[3] = ffma2(e2, make_float2(a1.z, a1.w), oacc[3]);
        }
    }

    // deterministic partial write
    float* pp = &g_part[((size_t)blockIdx.x * MAXB + (b_base + bb)) * FF + fh];
    pp[0] = oacc[0].x; pp[1] = oacc[0].y;
    pp[2] = oacc[1].x; pp[3] = oacc[1].y;
    pp[4] = oacc[2].x; pp[5] = oacc[2].y;
    pp[6] = oacc[3].x; pp[7] = oacc[3].y;
}

__global__ void reduce_out(float* __restrict__ out, int B) {
    int i = blockIdx.x * blockDim.x + threadIdx.x;
    if (i >= B * FF) return;
    int b = i / FF, f = i % FF;
    float sum = 0.f;
#pragma unroll 8
    for (int c = 0; c < NBX; c++)
        sum += g_part[((size_t)c * MAXB + b) * FF + f];
    out[i] = sum;
}

extern "C" void kernel_launch(void* const* d_in, const int* in_sizes, int n_in,
                              void* d_out, int out_size) {
    const float* z = (const float*)d_in[0];
    const float* x = (const float*)d_in[1];
    const float* alpha = (const float*)d_in[2];
    int B = in_sizes[0] / DD;   // 2048
    int N = in_sizes[1] / DD;   // 100000

    prep_norms<<<(N + B + 255) / 256, 256>>>(z, x, B, N);

    int ntiles = (N + NT - 1) / NT;
    int chunk = (ntiles + NBX - 1) / NBX;
    cudaFuncSetAttribute(rbf_main, cudaFuncAttributeMaxDynamicSharedMemorySize,
                         (int)sizeof(SmemT));
    dim3 grid(NBX, B / BT);
    rbf_main<<<grid, 256, sizeof(SmemT)>>>(z, x, alpha, B, N, ntiles, chunk);

    reduce_out<<<(B * FF + 255) / 256, 256>>>((float*)d_out, B);
}